// round 15
// baseline (speedup 1.0000x reference)
#include <cuda_runtime.h>
#include <cuda_fp16.h>
#include <math.h>
#include <stdint.h>

#define B_  8
#define S_  1024
#define D_  768
#define H_  12
#define DH_ 64
#define F_  3072
#define NROWS (B_*S_)   /* 8192 */

#define EPI_NONE    0
#define EPI_GELU    1
#define EPI_ADD     2
#define EPI_PARTIAL 3

// log2(e)/8 — folded into the Q projection (attention softmax in exp2 domain)
#define QSCALE 0.1803368801111204f

// ---------------------------------------------------------------------------
// Scratch (device globals — no allocation allowed)
// ---------------------------------------------------------------------------
__device__ __half g_h  [NROWS*D_];
__device__ __half g_q  [NROWS*D_];
__device__ __half g_k  [NROWS*D_];
__device__ __half g_v  [NROWS*D_];
__device__ __half g_ctx[NROWS*D_];
__device__ float  g_x2 [NROWS*D_];
__device__ __half g_ln2[NROWS*D_];
__device__ __half g_act[NROWS*F_];
__device__ float  g_split[2*NROWS*D_];   // split-K partial sums (fp32)
// fp16 weights, NATURAL layout [K][N]
#define WT_Q  0
#define WT_K  (768*768)
#define WT_V  (2*768*768)
#define WT_O  (3*768*768)
#define WT_W1 (4*768*768)
#define WT_W2 (4*768*768 + 768*3072)
__device__ __half g_wt [4*768*768 + 2*768*3072];

// ---------------------------------------------------------------------------
// helpers
// ---------------------------------------------------------------------------
__device__ __forceinline__ float gelu_f(float x) {
    return 0.5f * x * (1.0f + erff(x * 0.70710678118654752f));
}

__device__ __forceinline__ void mma_f16(
    float c[4], const unsigned a[4], const unsigned b[2])
{
    asm volatile(
        "mma.sync.aligned.m16n8k16.row.col.f32.f16.f16.f32 "
        "{%0,%1,%2,%3}, {%4,%5,%6,%7}, {%8,%9}, {%0,%1,%2,%3};"
        : "+f"(c[0]), "+f"(c[1]), "+f"(c[2]), "+f"(c[3])
        : "r"(a[0]), "r"(a[1]), "r"(a[2]), "r"(a[3]),
          "r"(b[0]), "r"(b[1]));
}

__device__ __forceinline__ void ldsm_x4(
    unsigned& r0, unsigned& r1, unsigned& r2, unsigned& r3, unsigned addr)
{
    asm volatile("ldmatrix.sync.aligned.m8n8.x4.shared.b16 {%0,%1,%2,%3}, [%4];"
                 : "=r"(r0), "=r"(r1), "=r"(r2), "=r"(r3) : "r"(addr));
}

__device__ __forceinline__ void ldsm_x4_trans(
    unsigned& r0, unsigned& r1, unsigned& r2, unsigned& r3, unsigned addr)
{
    asm volatile("ldmatrix.sync.aligned.m8n8.x4.trans.shared.b16 {%0,%1,%2,%3}, [%4];"
                 : "=r"(r0), "=r"(r1), "=r"(r2), "=r"(r3) : "r"(addr));
}

__device__ __forceinline__ unsigned pack_h2(float a, float b) {
    __half2 t = __floats2half2_rn(a, b);
    return *(unsigned*)&t;
}

__device__ __forceinline__ void cp_async16(unsigned smem_addr, const void* gptr) {
    asm volatile("cp.async.cg.shared.global [%0], [%1], 16;"
                 :: "r"(smem_addr), "l"(gptr));
}
__device__ __forceinline__ void cp_commit() {
    asm volatile("cp.async.commit_group;");
}
template<int N>
__device__ __forceinline__ void cp_wait() {
    asm volatile("cp.async.wait_group %0;" :: "n"(N));
}

// ---------------------------------------------------------------------------
// Weight convert (fp32 -> fp16, natural layout). One launch for all 6.
// ---------------------------------------------------------------------------
__global__ __launch_bounds__(256) void convert_w_kernel(
    const float* __restrict__ Wq, const float* __restrict__ Wk,
    const float* __restrict__ Wv, const float* __restrict__ Wo,
    const float* __restrict__ W1, const float* __restrict__ W2,
    __half* __restrict__ out)
{
    const int n1 = 768*768/2;
    const int n2 = 768*3072/2;
    const int total = 4*n1 + 2*n2;
    for (int i = blockIdx.x*blockDim.x + threadIdx.x; i < total;
         i += gridDim.x*blockDim.x) {
        const float2* src; int off;
        if (i < 4*n1) {
            int w = i / n1; off = i - w*n1;
            src = (const float2*)((w==0)?Wq:(w==1)?Wk:(w==2)?Wv:Wo);
        } else if (i < 4*n1 + n2) {
            src = (const float2*)W1; off = i - 4*n1;
        } else {
            src = (const float2*)W2; off = i - 4*n1 - n2;
        }
        float2 f = src[off];
        ((__half2*)out)[i] = __floats2half2_rn(f.x, f.y);
    }
}

// ---------------------------------------------------------------------------
// LayerNorm: warp-per-row, 8 rows/block, shuffle-only reduction.
// ---------------------------------------------------------------------------
__global__ __launch_bounds__(256) void ln_kernel(
    const float* __restrict__ x, const float* __restrict__ gam,
    const float* __restrict__ bet, __half* __restrict__ out)
{
    int warp = threadIdx.x >> 5, lane = threadIdx.x & 31;
    int row = blockIdx.x * 8 + warp;
    const float4* xr = (const float4*)(x + (size_t)row * D_);

    float4 vv[6];
    float s = 0.f, ss = 0.f;
    #pragma unroll
    for (int c = 0; c < 6; c++) {
        float4 t = xr[c*32 + lane];
        vv[c] = t;
        s  += t.x + t.y + t.z + t.w;
        ss += t.x*t.x + t.y*t.y + t.z*t.z + t.w*t.w;
    }
    #pragma unroll
    for (int o = 16; o > 0; o >>= 1) {
        s  += __shfl_xor_sync(0xffffffffu, s,  o);
        ss += __shfl_xor_sync(0xffffffffu, ss, o);
    }
    float mu  = s * (1.0f / D_);
    float var = ss * (1.0f / D_) - mu * mu;
    float inv = rsqrtf(var + 1e-6f);

    uint2* orow = (uint2*)(out + (size_t)row * D_);
    const float4* gg4 = (const float4*)gam;
    const float4* bb4 = (const float4*)bet;
    #pragma unroll
    for (int c = 0; c < 6; c++) {
        int idx = c*32 + lane;
        float4 gg = gg4[idx], bb = bb4[idx];
        float4 t = vv[c];
        float v0 = (t.x - mu) * inv * gg.x + bb.x;
        float v1 = (t.y - mu) * inv * gg.y + bb.y;
        float v2 = (t.z - mu) * inv * gg.z + bb.z;
        float v3 = (t.w - mu) * inv * gg.w + bb.w;
        uint2 o2;
        o2.x = pack_h2(v0, v1);
        o2.y = pack_h2(v2, v3);
        orow[idx] = o2;
    }
}

// ---------------------------------------------------------------------------
// split-K reduce: out = s0 + s1 + bias + res   (fp32, vectorized)
// total = NROWS*D_/4 float4 elements; D_/4 = 192 per row.
// ---------------------------------------------------------------------------
__global__ __launch_bounds__(256) void splitk_reduce_kernel(
    const float4* __restrict__ s0, const float4* __restrict__ s1,
    const float4* __restrict__ bias4, const float4* __restrict__ res,
    float4* __restrict__ out)
{
    int i = blockIdx.x * 256 + threadIdx.x;
    float4 a = s0[i], b = s1[i], r = res[i];
    float4 bb = bias4[i % (D_/4)];
    float4 o;
    o.x = a.x + b.x + r.x + bb.x;
    o.y = a.y + b.y + r.y + bb.y;
    o.z = a.z + b.z + r.z + bb.z;
    o.w = a.w + b.w + r.w + bb.w;
    out[i] = o;
}

// ---------------------------------------------------------------------------
// fp16 tensor-core GEMM: 128x128 tile, BK=64, 256 threads, warp tile 32x64.
// (R10-validated config, 2 CTAs/SM.) lda = A row stride (== total K for the
// unsplit case; == full K with a column offset for split-K).
// ---------------------------------------------------------------------------
#define BK 64
#define LDAH 72
#define LDBH 136
#define A_STG_H (128*LDAH)
#define B_STG_H (64*LDBH)
#define NSTG 3
#define GEMM_SMEM_BYTES (NSTG*(A_STG_H + B_STG_H)*2)   /* 107520 B */

template<int EPI>
__device__ __forceinline__ void h_gemm_body(
    const __half* __restrict__ A, const __half* __restrict__ W,
    const float* __restrict__ bias, const float* __restrict__ res,
    void* __restrict__ Cout, int M, int N, int K, int lda, float oscale)
{
    extern __shared__ __half hsm[];
    __half* As = hsm;
    __half* Bs = hsm + NSTG * A_STG_H;

    int tid  = threadIdx.x;
    int bm = blockIdx.y * 128, bn = blockIdx.x * 128;
    int lane = tid & 31, warp = tid >> 5;
    int warp_m = warp >> 1;
    int warp_n = warp & 1;
    int g  = lane >> 2;
    int tg = lane & 3;

    unsigned a_su[NSTG], b_su[NSTG];
    #pragma unroll
    for (int s = 0; s < NSTG; s++) {
        a_su[s] = (unsigned)__cvta_generic_to_shared(As + s * A_STG_H);
        b_su[s] = (unsigned)__cvta_generic_to_shared(Bs + s * B_STG_H);
    }

    int arow_off = (lane & 7) + ((lane >> 3) & 1) * 8;
    int ak_off   = ((lane >> 4) & 1) * 8;
    unsigned a_lm[2];
    #pragma unroll
    for (int mt = 0; mt < 2; mt++)
        a_lm[mt] = (unsigned)(((warp_m * 32 + mt * 16 + arow_off) * LDAH + ak_off) * 2);

    int trow = (lane & 7) + ((lane >> 3) & 1) * 8;
    int tcol = ((lane >> 4) & 1) * 8;
    unsigned b_lm[4];
    #pragma unroll
    for (int dp = 0; dp < 4; dp++)
        b_lm[dp] = (unsigned)((trow * LDBH + warp_n * 64 + dp * 16 + tcol) * 2);

    float acc[2][8][4];
    #pragma unroll
    for (int mt = 0; mt < 2; mt++)
        #pragma unroll
        for (int nt = 0; nt < 8; nt++)
            #pragma unroll
            for (int i = 0; i < 4; i++) acc[mt][nt][i] = 0.f;

    int nck = K / BK;

    auto issue = [&](int st, int ck) {
        int kb = ck * BK;
        #pragma unroll
        for (int p = 0; p < 4; p++) {
            int cid = tid + p * 256;
            int row = cid >> 3, c = cid & 7;
            unsigned off = (unsigned)((row * LDAH + c * 8) * 2);
            cp_async16(a_su[st] + off, A + (size_t)(bm + row) * lda + kb + c * 8);
        }
        #pragma unroll
        for (int p = 0; p < 4; p++) {
            int cid = tid + p * 256;
            int row = cid >> 4, c = cid & 15;
            unsigned off = (unsigned)((row * LDBH + c * 8) * 2);
            cp_async16(b_su[st] + off, W + (size_t)(kb + row) * N + bn + c * 8);
        }
        cp_commit();
    };

    issue(0, 0);
    if (nck > 1) issue(1, 1);

    for (int ck = 0; ck < nck; ck++) {
        int st = ck % 3;
        if (ck + 1 < nck) cp_wait<1>(); else cp_wait<0>();
        __syncthreads();
        if (ck + 2 < nck) issue((ck + 2) % 3, ck + 2);

        unsigned abase = a_su[st], bbase = b_su[st];

        #pragma unroll
        for (int ks = 0; ks < 4; ks++) {
            unsigned kadd_a = (unsigned)(ks * 16 * 2);
            unsigned kadd_b = (unsigned)(ks * 16 * LDBH * 2);
            unsigned af[2][4], bf[8][2];
            #pragma unroll
            for (int mt = 0; mt < 2; mt++)
                ldsm_x4(af[mt][0], af[mt][1], af[mt][2], af[mt][3],
                        abase + a_lm[mt] + kadd_a);
            #pragma unroll
            for (int dp = 0; dp < 4; dp++)
                ldsm_x4_trans(bf[2*dp][0], bf[2*dp][1], bf[2*dp+1][0], bf[2*dp+1][1],
                              bbase + b_lm[dp] + kadd_b);
            #pragma unroll
            for (int mt = 0; mt < 2; mt++)
                #pragma unroll
                for (int nt = 0; nt < 8; nt++)
                    mma_f16(acc[mt][nt], af[mt], bf[nt]);
        }
    }
    __syncthreads();

    #pragma unroll
    for (int mt = 0; mt < 2; mt++) {
        #pragma unroll
        for (int nt = 0; nt < 8; nt++) {
            int row0 = bm + warp_m * 32 + mt * 16 + g;
            int row1 = row0 + 8;
            int col  = bn + warp_n * 64 + nt * 8 + tg * 2;
            if (EPI == EPI_PARTIAL) {
                float* C = (float*)Cout;
                *(float2*)&C[(size_t)row0 * N + col] =
                    make_float2(acc[mt][nt][0], acc[mt][nt][1]);
                *(float2*)&C[(size_t)row1 * N + col] =
                    make_float2(acc[mt][nt][2], acc[mt][nt][3]);
                continue;
            }
            float2 bb = *(const float2*)&bias[col];
            float v0 = acc[mt][nt][0] + bb.x;
            float v1 = acc[mt][nt][1] + bb.y;
            float v2 = acc[mt][nt][2] + bb.x;
            float v3 = acc[mt][nt][3] + bb.y;
            if (EPI == EPI_GELU) {
                v0 = gelu_f(v0); v1 = gelu_f(v1);
                v2 = gelu_f(v2); v3 = gelu_f(v3);
            }
            if (EPI == EPI_ADD) {
                float* C = (float*)Cout;
                float2 r0 = *(const float2*)&res[(size_t)row0 * N + col];
                float2 r1 = *(const float2*)&res[(size_t)row1 * N + col];
                v0 += r0.x; v1 += r0.y; v2 += r1.x; v3 += r1.y;
                *(float2*)&C[(size_t)row0 * N + col] = make_float2(v0, v1);
                *(float2*)&C[(size_t)row1 * N + col] = make_float2(v2, v3);
            } else {
                v0 *= oscale; v1 *= oscale; v2 *= oscale; v3 *= oscale;
                __half* C = (__half*)Cout;
                *(__half2*)&C[(size_t)row0 * N + col] = __floats2half2_rn(v0, v1);
                *(__half2*)&C[(size_t)row1 * N + col] = __floats2half2_rn(v2, v3);
            }
        }
    }
}

template<int EPI>
__global__ __launch_bounds__(256, 2) void h_gemm_kernel(
    const __half* __restrict__ A, const __half* __restrict__ W,
    const float* __restrict__ bias, const float* __restrict__ res,
    void* __restrict__ Cout, int M, int N, int K)
{
    h_gemm_body<EPI>(A, W, bias, res, Cout, M, N, K, K, 1.0f);
}

__global__ __launch_bounds__(256, 2) void h_qkv_kernel(
    const __half* __restrict__ A, const __half* __restrict__ wt,
    const float* __restrict__ bq, const float* __restrict__ bk, const float* __restrict__ bv,
    __half* __restrict__ Cq, __half* __restrict__ Ck, __half* __restrict__ Cv)
{
    const __half* W   = wt + (size_t)blockIdx.z * (768 * 768);
    const float*  bia = (blockIdx.z == 0) ? bq : (blockIdx.z == 1) ? bk : bv;
    __half*       C   = (blockIdx.z == 0) ? Cq : (blockIdx.z == 1) ? Ck : Cv;
    float         sc  = (blockIdx.z == 0) ? QSCALE : 1.0f;
    h_gemm_body<EPI_NONE>(A, W, bia, nullptr, (void*)C, NROWS, D_, D_, D_, sc);
}

// split-K=2: blockIdx.z selects K-half; fp32 partial output (no bias/res).
__global__ __launch_bounds__(256, 2) void h_gemm_splitk_kernel(
    const __half* __restrict__ A, const __half* __restrict__ W,
    float* __restrict__ Cpart, int M, int N, int Ktot)
{
    int kz = blockIdx.z;
    int Khalf = Ktot >> 1;
    const __half* Ao = A + (size_t)kz * Khalf;           // column offset, stride Ktot
    const __half* Wo = W + (size_t)kz * Khalf * N;
    float* Co = Cpart + (size_t)kz * M * N;
    h_gemm_body<EPI_PARTIAL>(Ao, Wo, nullptr, nullptr, (void*)Co,
                             M, N, Khalf, Ktot, 1.0f);
}

// ---------------------------------------------------------------------------
// Fused attention, register flash + cp.async double-buffered K/V, single
// barrier per tile, exp2-domain softmax (validated R13).
// ---------------------------------------------------------------------------
#define LQ 72
struct AttnSmem {
    __half Qh[128][LQ];
    __half Kh[2][64][LQ];
    __half Vh[2][64][LQ];
};
#define ATTN_SMEM_BYTES ((int)sizeof(AttnSmem))

__global__ __launch_bounds__(256, 2) void attn_kernel(
    const __half* __restrict__ q, const __half* __restrict__ k,
    const __half* __restrict__ v, __half* __restrict__ ctx)
{
    extern __shared__ char smem_raw[];
    AttnSmem& S = *(AttnSmem*)smem_raw;
    int bb = blockIdx.z, hh = blockIdx.y;
    int q0 = blockIdx.x * 128;
    int tid = threadIdx.x;
    int lane = tid & 31, wid = tid >> 5;
    int g = lane >> 2, tg = lane & 3;
    int m0 = wid * 16;

    unsigned k_su[2], v_su[2];
    #pragma unroll
    for (int bi = 0; bi < 2; bi++) {
        k_su[bi] = (unsigned)__cvta_generic_to_shared(&S.Kh[bi][0][0]);
        v_su[bi] = (unsigned)__cvta_generic_to_shared(&S.Vh[bi][0][0]);
    }

    auto issue_kv = [&](int bi, int kt) {
        int k0g = kt * 64;
        #pragma unroll
        for (int i = 0; i < 2; i++) {
            int cid = tid + i * 256;
            int row = cid >> 3, c = cid & 7;
            unsigned off = (unsigned)((row * LQ + c * 8) * 2);
            size_t base = ((size_t)((bb*S_ + k0g + row)*H_ + hh))*DH_ + c*8;
            cp_async16(k_su[bi] + off, k + base);
            cp_async16(v_su[bi] + off, v + base);
        }
        cp_commit();
    };

    {
        #pragma unroll
        for (int i = 0; i < 4; i++) {
            int cid = tid + i * 256;
            int row = cid >> 3, c = cid & 7;
            const __half* gq = q + ((size_t)((bb*S_ + q0 + row)*H_ + hh))*DH_ + c*8;
            *(uint4*)&S.Qh[row][c*8] = *(const uint4*)gq;
        }
    }
    issue_kv(0, 0);

    int arow = (lane & 7) + ((lane >> 3) & 1) * 8;
    int acol = ((lane >> 4) & 1) * 8;
    int brow = (lane & 7) + ((lane >> 4) & 1) * 8;
    int bcol = ((lane >> 3) & 1) * 8;

    unsigned q_lm = (unsigned)__cvta_generic_to_shared(&S.Qh[m0 + arow][acol]);
    unsigned k_lm[2][4], v_lm[2][4][4];
    #pragma unroll
    for (int bi = 0; bi < 2; bi++) {
        #pragma unroll
        for (int p = 0; p < 4; p++)
            k_lm[bi][p] = (unsigned)__cvta_generic_to_shared(
                &S.Kh[bi][p*16 + brow][bcol]);
        #pragma unroll
        for (int ks = 0; ks < 4; ks++)
            #pragma unroll
            for (int dp = 0; dp < 4; dp++)
                v_lm[bi][ks][dp] = (unsigned)__cvta_generic_to_shared(
                    &S.Vh[bi][ks*16 + arow][dp*16 + acol]);
    }

    float m_r[2] = {-1e30f, -1e30f};
    float l_r[2] = {0.f, 0.f};
    float o[8][4];
    #pragma unroll
    for (int nt = 0; nt < 8; nt++)
        #pragma unroll
        for (int i = 0; i < 4; i++) o[nt][i] = 0.f;

    __syncthreads();

    unsigned aq[4][4];
    #pragma unroll
    for (int ks = 0; ks < 4; ks++)
        ldsm_x4(aq[ks][0], aq[ks][1], aq[ks][2], aq[ks][3], q_lm + ks*32);

    const int NKT = S_/64;
    for (int kt = 0; kt < NKT; kt++) {
        int bi = kt & 1;
        cp_wait<0>();
        __syncthreads();
        if (kt + 1 < NKT) issue_kv(bi ^ 1, kt + 1);

        float s[8][4];
        #pragma unroll
        for (int nt = 0; nt < 8; nt++)
            #pragma unroll
            for (int i = 0; i < 4; i++) s[nt][i] = 0.f;
        #pragma unroll
        for (int ks = 0; ks < 4; ks++) {
            unsigned bf[8][2];
            #pragma unroll
            for (int p = 0; p < 4; p++)
                ldsm_x4(bf[2*p][0], bf[2*p][1], bf[2*p+1][0], bf[2*p+1][1],
                        k_lm[bi][p] + ks*32);
            #pragma unroll
            for (int nt = 0; nt < 8; nt++)
                mma_f16(s[nt], aq[ks], bf[nt]);
        }

        #pragma unroll
        for (int r = 0; r < 2; r++) {
            float mx = -1e30f;
            #pragma unroll
            for (int nt = 0; nt < 8; nt++)
                mx = fmaxf(mx, fmaxf(s[nt][2*r], s[nt][2*r+1]));
            mx = fmaxf(mx, __shfl_xor_sync(0xffffffffu, mx, 1));
            mx = fmaxf(mx, __shfl_xor_sync(0xffffffffu, mx, 2));
            float mn = fmaxf(m_r[r], mx);
            float cr = exp2f(m_r[r] - mn);
            m_r[r] = mn;
            float ls = 0.f;
            #pragma unroll
            for (int nt = 0; nt < 8; nt++) {
                float p0 = exp2f(s[nt][2*r    ] - mn);
                float p1 = exp2f(s[nt][2*r + 1] - mn);
                s[nt][2*r] = p0; s[nt][2*r+1] = p1;
                ls += p0 + p1;
            }
            ls += __shfl_xor_sync(0xffffffffu, ls, 1);
            ls += __shfl_xor_sync(0xffffffffu, ls, 2);
            l_r[r] = l_r[r] * cr + ls;
            #pragma unroll
            for (int nt = 0; nt < 8; nt++) {
                o[nt][2*r] *= cr; o[nt][2*r+1] *= cr;
            }
        }

        unsigned pa[4][4];
        #pragma unroll
        for (int ks = 0; ks < 4; ks++) {
            pa[ks][0] = pack_h2(s[2*ks  ][0], s[2*ks  ][1]);
            pa[ks][1] = pack_h2(s[2*ks  ][2], s[2*ks  ][3]);
            pa[ks][2] = pack_h2(s[2*ks+1][0], s[2*ks+1][1]);
            pa[ks][3] = pack_h2(s[2*ks+1][2], s[2*ks+1][3]);
        }

        #pragma unroll
        for (int ks = 0; ks < 4; ks++) {
            unsigned vf[8][2];
            #pragma unroll
            for (int dp = 0; dp < 4; dp++)
                ldsm_x4_trans(vf[2*dp][0], vf[2*dp][1], vf[2*dp+1][0], vf[2*dp+1][1],
                              v_lm[bi][ks][dp]);
            #pragma unroll
            for (int nt = 0; nt < 8; nt++)
                mma_f16(o[nt], pa[ks], vf[nt]);
        }
    }

    float inv0 = 1.0f / l_r[0];
    float inv1 = 1.0f / l_r[1];
    int row0 = bb*S_ + q0 + m0 + g;
    int row1 = row0 + 8;
    #pragma unroll
    for (int nt = 0; nt < 8; nt++) {
        int d = nt * 8 + tg * 2;
        *(__half2*)&ctx[((size_t)(row0*H_ + hh))*DH_ + d] =
            __floats2half2_rn(o[nt][0] * inv0, o[nt][1] * inv0);
        *(__half2*)&ctx[((size_t)(row1*H_ + hh))*DH_ + d] =
            __floats2half2_rn(o[nt][2] * inv1, o[nt][3] * inv1);
    }
}

// ---------------------------------------------------------------------------
// Launcher
// ---------------------------------------------------------------------------
extern "C" void kernel_launch(void* const* d_in, const int* in_sizes, int n_in,
                              void* d_out, int out_size)
{
    const float* x   = (const float*)d_in[0];
    const float* Wq  = (const float*)d_in[1];
    const float* bq  = (const float*)d_in[2];
    const float* Wk  = (const float*)d_in[3];
    const float* bk  = (const float*)d_in[4];
    const float* Wv  = (const float*)d_in[5];
    const float* bv  = (const float*)d_in[6];
    const float* Wo  = (const float*)d_in[7];
    const float* bo  = (const float*)d_in[8];
    const float* g1  = (const float*)d_in[9];
    const float* be1 = (const float*)d_in[10];
    const float* g2  = (const float*)d_in[11];
    const float* be2 = (const float*)d_in[12];
    const float* W1  = (const float*)d_in[13];
    const float* b1  = (const float*)d_in[14];
    const float* W2  = (const float*)d_in[15];
    const float* b2  = (const float*)d_in[16];
    float* out = (float*)d_out;

    __half *h, *q, *k, *v, *ctx, *ln2, *act, *wt;
    float *x2, *split;
    cudaGetSymbolAddress((void**)&h,    g_h);
    cudaGetSymbolAddress((void**)&q,    g_q);
    cudaGetSymbolAddress((void**)&k,    g_k);
    cudaGetSymbolAddress((void**)&v,    g_v);
    cudaGetSymbolAddress((void**)&ctx,  g_ctx);
    cudaGetSymbolAddress((void**)&x2,   g_x2);
    cudaGetSymbolAddress((void**)&ln2,  g_ln2);
    cudaGetSymbolAddress((void**)&act,  g_act);
    cudaGetSymbolAddress((void**)&wt,   g_wt);
    cudaGetSymbolAddress((void**)&split, g_split);

    cudaFuncSetAttribute(h_gemm_kernel<EPI_ADD>,
                         cudaFuncAttributeMaxDynamicSharedMemorySize, GEMM_SMEM_BYTES);
    cudaFuncSetAttribute(h_gemm_kernel<EPI_GELU>,
                         cudaFuncAttributeMaxDynamicSharedMemorySize, GEMM_SMEM_BYTES);
    cudaFuncSetAttribute(h_qkv_kernel,
                         cudaFuncAttributeMaxDynamicSharedMemorySize, GEMM_SMEM_BYTES);
    cudaFuncSetAttribute(h_gemm_splitk_kernel,
                         cudaFuncAttributeMaxDynamicSharedMemorySize, GEMM_SMEM_BYTES);
    cudaFuncSetAttribute(attn_kernel,
                         cudaFuncAttributeMaxDynamicSharedMemorySize, ATTN_SMEM_BYTES);

    // 0. weight fp32->fp16 convert (natural layout), single launch
    convert_w_kernel<<<2048, 256>>>(Wq, Wk, Wv, Wo, W1, W2, wt);

    // 1. pre-LN -> fp16 h
    ln_kernel<<<NROWS/8, 256>>>(x, g1, be1, h);
    // 2. QKV (fp16 mma, batched; Q scaled by log2e/8 in epilogue)
    dim3 gqkv(D_/128, NROWS/128, 3);
    h_qkv_kernel<<<gqkv, 256, GEMM_SMEM_BYTES>>>(h, wt, bq, bk, bv, q, k, v);
    // 3. fused attention (exp2-domain softmax) -> fp16 ctx
    dim3 gat(S_/128, H_, B_);
    attn_kernel<<<gat, 256, ATTN_SMEM_BYTES>>>(q, k, v, ctx);
    // 4. Wo projection + residual -> fp32 x2
    dim3 go(D_/128, NROWS/128);
    h_gemm_kernel<EPI_ADD><<<go, 256, GEMM_SMEM_BYTES>>>(ctx, wt + WT_O, bo, x, (void*)x2, NROWS, D_, D_);
    // 5. LN2 -> fp16 ln2
    ln_kernel<<<NROWS/8, 256>>>(x2, g2, be2, ln2);
    // 6. MLP up + exact GELU -> fp16 act
    dim3 gup(F_/128, NROWS/128);
    h_gemm_kernel<EPI_GELU><<<gup, 256, GEMM_SMEM_BYTES>>>(ln2, wt + WT_W1, b1, nullptr, (void*)act, NROWS, F_, D_);
    // 7. MLP down, split-K=2 -> fp32 partials, then reduce (+bias+residual) -> out
    dim3 gdn(D_/128, NROWS/128, 2);
    h_gemm_splitk_kernel<<<gdn, 256, GEMM_SMEM_BYTES>>>(act, wt + WT_W2, split, NROWS, D_, F_);
    splitk_reduce_kernel<<<NROWS*D_/4/256, 256>>>(
        (const float4*)split, (const float4*)(split + (size_t)NROWS*D_),
        (const float4*)b2, (const float4*)x2, (float4*)out);
}

// round 17
// speedup vs baseline: 1.0191x; 1.0191x over previous
#include <cuda_runtime.h>
#include <cuda_fp16.h>
#include <math.h>
#include <stdint.h>

#define B_  8
#define S_  1024
#define D_  768
#define H_  12
#define DH_ 64
#define F_  3072
#define NROWS (B_*S_)   /* 8192 */

#define EPI_NONE 0
#define EPI_GELU 1
#define EPI_ADD  2

// log2(e)/8 — folded into the Q projection (attention softmax in exp2 domain)
#define QSCALE 0.1803368801111204f

// ---------------------------------------------------------------------------
// Scratch (device globals — no allocation allowed)
// ---------------------------------------------------------------------------
__device__ __half g_h  [NROWS*D_];
__device__ __half g_q  [NROWS*D_];
__device__ __half g_k  [NROWS*D_];
__device__ __half g_v  [NROWS*D_];
__device__ __half g_ctx[NROWS*D_];
__device__ float  g_x2 [NROWS*D_];
__device__ __half g_ln2[NROWS*D_];
__device__ __half g_act[NROWS*F_];
// fp16 weights, NATURAL layout [K][N]
#define WT_Q  0
#define WT_K  (768*768)
#define WT_V  (2*768*768)
#define WT_O  (3*768*768)
#define WT_W1 (4*768*768)
#define WT_W2 (4*768*768 + 768*3072)
__device__ __half g_wt [4*768*768 + 2*768*3072];

// ---------------------------------------------------------------------------
// helpers
// ---------------------------------------------------------------------------
__device__ __forceinline__ float gelu_f(float x) {
    return 0.5f * x * (1.0f + erff(x * 0.70710678118654752f));
}

__device__ __forceinline__ float fast_exp2(float x) {
    float y;
    asm("ex2.approx.ftz.f32 %0, %1;" : "=f"(y) : "f"(x));
    return y;
}

__device__ __forceinline__ void mma_f16(
    float c[4], const unsigned a[4], const unsigned b[2])
{
    asm volatile(
        "mma.sync.aligned.m16n8k16.row.col.f32.f16.f16.f32 "
        "{%0,%1,%2,%3}, {%4,%5,%6,%7}, {%8,%9}, {%0,%1,%2,%3};"
        : "+f"(c[0]), "+f"(c[1]), "+f"(c[2]), "+f"(c[3])
        : "r"(a[0]), "r"(a[1]), "r"(a[2]), "r"(a[3]),
          "r"(b[0]), "r"(b[1]));
}

__device__ __forceinline__ void ldsm_x4(
    unsigned& r0, unsigned& r1, unsigned& r2, unsigned& r3, unsigned addr)
{
    asm volatile("ldmatrix.sync.aligned.m8n8.x4.shared.b16 {%0,%1,%2,%3}, [%4];"
                 : "=r"(r0), "=r"(r1), "=r"(r2), "=r"(r3) : "r"(addr));
}

__device__ __forceinline__ void ldsm_x4_trans(
    unsigned& r0, unsigned& r1, unsigned& r2, unsigned& r3, unsigned addr)
{
    asm volatile("ldmatrix.sync.aligned.m8n8.x4.trans.shared.b16 {%0,%1,%2,%3}, [%4];"
                 : "=r"(r0), "=r"(r1), "=r"(r2), "=r"(r3) : "r"(addr));
}

__device__ __forceinline__ unsigned pack_h2(float a, float b) {
    __half2 t = __floats2half2_rn(a, b);
    return *(unsigned*)&t;
}

__device__ __forceinline__ void cp_async16(unsigned smem_addr, const void* gptr) {
    asm volatile("cp.async.cg.shared.global [%0], [%1], 16;"
                 :: "r"(smem_addr), "l"(gptr));
}
__device__ __forceinline__ void cp_commit() {
    asm volatile("cp.async.commit_group;");
}
template<int N>
__device__ __forceinline__ void cp_wait() {
    asm volatile("cp.async.wait_group %0;" :: "n"(N));
}

// ---------------------------------------------------------------------------
// LayerNorm body: warp-per-row, shuffle-only reduction (device fn, shared by
// the fused prep kernel and the standalone LN2 kernel).
// ---------------------------------------------------------------------------
__device__ __forceinline__ void ln_row(
    const float* __restrict__ x, const float* __restrict__ gam,
    const float* __restrict__ bet, __half* __restrict__ out, int row, int lane)
{
    const float4* xr = (const float4*)(x + (size_t)row * D_);
    float4 vv[6];
    float s = 0.f, ss = 0.f;
    #pragma unroll
    for (int c = 0; c < 6; c++) {
        float4 t = xr[c*32 + lane];
        vv[c] = t;
        s  += t.x + t.y + t.z + t.w;
        ss += t.x*t.x + t.y*t.y + t.z*t.z + t.w*t.w;
    }
    #pragma unroll
    for (int o = 16; o > 0; o >>= 1) {
        s  += __shfl_xor_sync(0xffffffffu, s,  o);
        ss += __shfl_xor_sync(0xffffffffu, ss, o);
    }
    float mu  = s * (1.0f / D_);
    float var = ss * (1.0f / D_) - mu * mu;
    float inv = rsqrtf(var + 1e-6f);

    uint2* orow = (uint2*)(out + (size_t)row * D_);
    const float4* gg4 = (const float4*)gam;
    const float4* bb4 = (const float4*)bet;
    #pragma unroll
    for (int c = 0; c < 6; c++) {
        int idx = c*32 + lane;
        float4 gg = gg4[idx], bb = bb4[idx];
        float4 t = vv[c];
        uint2 o2;
        o2.x = pack_h2((t.x - mu) * inv * gg.x + bb.x,
                       (t.y - mu) * inv * gg.y + bb.y);
        o2.y = pack_h2((t.z - mu) * inv * gg.z + bb.z,
                       (t.w - mu) * inv * gg.w + bb.w);
        orow[idx] = o2;
    }
}

__global__ __launch_bounds__(256) void ln_kernel(
    const float* __restrict__ x, const float* __restrict__ gam,
    const float* __restrict__ bet, __half* __restrict__ out)
{
    ln_row(x, gam, bet, out, blockIdx.x * 8 + (threadIdx.x >> 5),
           threadIdx.x & 31);
}

// ---------------------------------------------------------------------------
// Fused prep: blocks [0, NROWS/8) run LN1; remaining blocks convert the six
// fp32 weight matrices to fp16 (natural layout). The two are independent and
// overlap inside one launch.
// ---------------------------------------------------------------------------
#define LN_BLKS (NROWS/8)          /* 1024 */
#define CV_BLKS 2048
__global__ __launch_bounds__(256) void prep_kernel(
    const float* __restrict__ x, const float* __restrict__ g1,
    const float* __restrict__ be1, __half* __restrict__ h,
    const float* __restrict__ Wq, const float* __restrict__ Wk,
    const float* __restrict__ Wv, const float* __restrict__ Wo,
    const float* __restrict__ W1, const float* __restrict__ W2,
    __half* __restrict__ wt)
{
    if (blockIdx.x < LN_BLKS) {
        ln_row(x, g1, be1, h, blockIdx.x * 8 + (threadIdx.x >> 5),
               threadIdx.x & 31);
        return;
    }
    const int n1 = 768*768/2;
    const int n2 = 768*3072/2;
    const int total = 4*n1 + 2*n2;
    int base = (blockIdx.x - LN_BLKS) * 256 + threadIdx.x;
    for (int i = base; i < total; i += CV_BLKS * 256) {
        const float2* src; int off;
        if (i < 4*n1) {
            int w = i / n1; off = i - w*n1;
            src = (const float2*)((w==0)?Wq:(w==1)?Wk:(w==2)?Wv:Wo);
        } else if (i < 4*n1 + n2) {
            src = (const float2*)W1; off = i - 4*n1;
        } else {
            src = (const float2*)W2; off = i - 4*n1 - n2;
        }
        float2 f = src[off];
        ((__half2*)wt)[i] = __floats2half2_rn(f.x, f.y);
    }
}

// ---------------------------------------------------------------------------
// fp16 tensor-core GEMM: 128x128 tile, BK=64, 256 threads, warp tile 32x64.
// (R10-validated config, 2 CTAs/SM.)
// ---------------------------------------------------------------------------
#define BK 64
#define LDAH 72
#define LDBH 136
#define A_STG_H (128*LDAH)
#define B_STG_H (64*LDBH)
#define NSTG 3
#define GEMM_SMEM_BYTES (NSTG*(A_STG_H + B_STG_H)*2)   /* 107520 B */

template<int EPI>
__device__ __forceinline__ void h_gemm_body(
    const __half* __restrict__ A, const __half* __restrict__ W,
    const float* __restrict__ bias, const float* __restrict__ res,
    void* __restrict__ Cout, int M, int N, int K, float oscale)
{
    extern __shared__ __half hsm[];
    __half* As = hsm;
    __half* Bs = hsm + NSTG * A_STG_H;

    int tid  = threadIdx.x;
    int bm = blockIdx.y * 128, bn = blockIdx.x * 128;
    int lane = tid & 31, warp = tid >> 5;
    int warp_m = warp >> 1;
    int warp_n = warp & 1;
    int g  = lane >> 2;
    int tg = lane & 3;

    unsigned a_su[NSTG], b_su[NSTG];
    #pragma unroll
    for (int s = 0; s < NSTG; s++) {
        a_su[s] = (unsigned)__cvta_generic_to_shared(As + s * A_STG_H);
        b_su[s] = (unsigned)__cvta_generic_to_shared(Bs + s * B_STG_H);
    }

    int arow_off = (lane & 7) + ((lane >> 3) & 1) * 8;
    int ak_off   = ((lane >> 4) & 1) * 8;
    unsigned a_lm[2];
    #pragma unroll
    for (int mt = 0; mt < 2; mt++)
        a_lm[mt] = (unsigned)(((warp_m * 32 + mt * 16 + arow_off) * LDAH + ak_off) * 2);

    int trow = (lane & 7) + ((lane >> 3) & 1) * 8;
    int tcol = ((lane >> 4) & 1) * 8;
    unsigned b_lm[4];
    #pragma unroll
    for (int dp = 0; dp < 4; dp++)
        b_lm[dp] = (unsigned)((trow * LDBH + warp_n * 64 + dp * 16 + tcol) * 2);

    float acc[2][8][4];
    #pragma unroll
    for (int mt = 0; mt < 2; mt++)
        #pragma unroll
        for (int nt = 0; nt < 8; nt++)
            #pragma unroll
            for (int i = 0; i < 4; i++) acc[mt][nt][i] = 0.f;

    int nck = K / BK;

    auto issue = [&](int st, int ck) {
        int kb = ck * BK;
        #pragma unroll
        for (int p = 0; p < 4; p++) {
            int cid = tid + p * 256;
            int row = cid >> 3, c = cid & 7;
            unsigned off = (unsigned)((row * LDAH + c * 8) * 2);
            cp_async16(a_su[st] + off, A + (size_t)(bm + row) * K + kb + c * 8);
        }
        #pragma unroll
        for (int p = 0; p < 4; p++) {
            int cid = tid + p * 256;
            int row = cid >> 4, c = cid & 15;
            unsigned off = (unsigned)((row * LDBH + c * 8) * 2);
            cp_async16(b_su[st] + off, W + (size_t)(kb + row) * N + bn + c * 8);
        }
        cp_commit();
    };

    issue(0, 0);
    if (nck > 1) issue(1, 1);

    for (int ck = 0; ck < nck; ck++) {
        int st = ck % 3;
        if (ck + 1 < nck) cp_wait<1>(); else cp_wait<0>();
        __syncthreads();
        if (ck + 2 < nck) issue((ck + 2) % 3, ck + 2);

        unsigned abase = a_su[st], bbase = b_su[st];

        #pragma unroll
        for (int ks = 0; ks < 4; ks++) {
            unsigned kadd_a = (unsigned)(ks * 16 * 2);
            unsigned kadd_b = (unsigned)(ks * 16 * LDBH * 2);
            unsigned af[2][4], bf[8][2];
            #pragma unroll
            for (int mt = 0; mt < 2; mt++)
                ldsm_x4(af[mt][0], af[mt][1], af[mt][2], af[mt][3],
                        abase + a_lm[mt] + kadd_a);
            #pragma unroll
            for (int dp = 0; dp < 4; dp++)
                ldsm_x4_trans(bf[2*dp][0], bf[2*dp][1], bf[2*dp+1][0], bf[2*dp+1][1],
                              bbase + b_lm[dp] + kadd_b);
            #pragma unroll
            for (int mt = 0; mt < 2; mt++)
                #pragma unroll
                for (int nt = 0; nt < 8; nt++)
                    mma_f16(acc[mt][nt], af[mt], bf[nt]);
        }
    }
    __syncthreads();

    #pragma unroll
    for (int mt = 0; mt < 2; mt++) {
        #pragma unroll
        for (int nt = 0; nt < 8; nt++) {
            int row0 = bm + warp_m * 32 + mt * 16 + g;
            int row1 = row0 + 8;
            int col  = bn + warp_n * 64 + nt * 8 + tg * 2;
            float2 bb = *(const float2*)&bias[col];
            float v0 = acc[mt][nt][0] + bb.x;
            float v1 = acc[mt][nt][1] + bb.y;
            float v2 = acc[mt][nt][2] + bb.x;
            float v3 = acc[mt][nt][3] + bb.y;
            if (EPI == EPI_GELU) {
                v0 = gelu_f(v0); v1 = gelu_f(v1);
                v2 = gelu_f(v2); v3 = gelu_f(v3);
            }
            if (EPI == EPI_ADD) {
                float* C = (float*)Cout;
                float2 r0 = *(const float2*)&res[(size_t)row0 * N + col];
                float2 r1 = *(const float2*)&res[(size_t)row1 * N + col];
                v0 += r0.x; v1 += r0.y; v2 += r1.x; v3 += r1.y;
                *(float2*)&C[(size_t)row0 * N + col] = make_float2(v0, v1);
                *(float2*)&C[(size_t)row1 * N + col] = make_float2(v2, v3);
            } else {
                v0 *= oscale; v1 *= oscale; v2 *= oscale; v3 *= oscale;
                __half* C = (__half*)Cout;
                *(__half2*)&C[(size_t)row0 * N + col] = __floats2half2_rn(v0, v1);
                *(__half2*)&C[(size_t)row1 * N + col] = __floats2half2_rn(v2, v3);
            }
        }
    }
}

template<int EPI>
__global__ __launch_bounds__(256, 2) void h_gemm_kernel(
    const __half* __restrict__ A, const __half* __restrict__ W,
    const float* __restrict__ bias, const float* __restrict__ res,
    void* __restrict__ Cout, int M, int N, int K)
{
    h_gemm_body<EPI>(A, W, bias, res, Cout, M, N, K, 1.0f);
}

__global__ __launch_bounds__(256, 2) void h_qkv_kernel(
    const __half* __restrict__ A, const __half* __restrict__ wt,
    const float* __restrict__ bq, const float* __restrict__ bk, const float* __restrict__ bv,
    __half* __restrict__ Cq, __half* __restrict__ Ck, __half* __restrict__ Cv)
{
    const __half* W   = wt + (size_t)blockIdx.z * (768 * 768);
    const float*  bia = (blockIdx.z == 0) ? bq : (blockIdx.z == 1) ? bk : bv;
    __half*       C   = (blockIdx.z == 0) ? Cq : (blockIdx.z == 1) ? Ck : Cv;
    float         sc  = (blockIdx.z == 0) ? QSCALE : 1.0f;
    h_gemm_body<EPI_NONE>(A, W, bia, nullptr, (void*)C, NROWS, D_, D_, sc);
}

// ---------------------------------------------------------------------------
// Fused attention, register flash + cp.async double-buffered K/V, single
// barrier per tile, exp2-domain softmax with raw MUFU.EX2.
// ---------------------------------------------------------------------------
#define LQ 72
struct AttnSmem {
    __half Qh[128][LQ];
    __half Kh[2][64][LQ];
    __half Vh[2][64][LQ];
};
#define ATTN_SMEM_BYTES ((int)sizeof(AttnSmem))

__global__ __launch_bounds__(256, 2) void attn_kernel(
    const __half* __restrict__ q, const __half* __restrict__ k,
    const __half* __restrict__ v, __half* __restrict__ ctx)
{
    extern __shared__ char smem_raw[];
    AttnSmem& S = *(AttnSmem*)smem_raw;
    int bb = blockIdx.z, hh = blockIdx.y;
    int q0 = blockIdx.x * 128;
    int tid = threadIdx.x;
    int lane = tid & 31, wid = tid >> 5;
    int g = lane >> 2, tg = lane & 3;
    int m0 = wid * 16;

    unsigned k_su[2], v_su[2];
    #pragma unroll
    for (int bi = 0; bi < 2; bi++) {
        k_su[bi] = (unsigned)__cvta_generic_to_shared(&S.Kh[bi][0][0]);
        v_su[bi] = (unsigned)__cvta_generic_to_shared(&S.Vh[bi][0][0]);
    }

    auto issue_kv = [&](int bi, int kt) {
        int k0g = kt * 64;
        #pragma unroll
        for (int i = 0; i < 2; i++) {
            int cid = tid + i * 256;
            int row = cid >> 3, c = cid & 7;
            unsigned off = (unsigned)((row * LQ + c * 8) * 2);
            size_t base = ((size_t)((bb*S_ + k0g + row)*H_ + hh))*DH_ + c*8;
            cp_async16(k_su[bi] + off, k + base);
            cp_async16(v_su[bi] + off, v + base);
        }
        cp_commit();
    };

    {
        #pragma unroll
        for (int i = 0; i < 4; i++) {
            int cid = tid + i * 256;
            int row = cid >> 3, c = cid & 7;
            const __half* gq = q + ((size_t)((bb*S_ + q0 + row)*H_ + hh))*DH_ + c*8;
            *(uint4*)&S.Qh[row][c*8] = *(const uint4*)gq;
        }
    }
    issue_kv(0, 0);

    int arow = (lane & 7) + ((lane >> 3) & 1) * 8;
    int acol = ((lane >> 4) & 1) * 8;
    int brow = (lane & 7) + ((lane >> 4) & 1) * 8;
    int bcol = ((lane >> 3) & 1) * 8;

    unsigned q_lm = (unsigned)__cvta_generic_to_shared(&S.Qh[m0 + arow][acol]);
    unsigned k_lm[2][4], v_lm[2][4][4];
    #pragma unroll
    for (int bi = 0; bi < 2; bi++) {
        #pragma unroll
        for (int p = 0; p < 4; p++)
            k_lm[bi][p] = (unsigned)__cvta_generic_to_shared(
                &S.Kh[bi][p*16 + brow][bcol]);
        #pragma unroll
        for (int ks = 0; ks < 4; ks++)
            #pragma unroll
            for (int dp = 0; dp < 4; dp++)
                v_lm[bi][ks][dp] = (unsigned)__cvta_generic_to_shared(
                    &S.Vh[bi][ks*16 + arow][dp*16 + acol]);
    }

    float m_r[2] = {-1e30f, -1e30f};
    float l_r[2] = {0.f, 0.f};
    float o[8][4];
    #pragma unroll
    for (int nt = 0; nt < 8; nt++)
        #pragma unroll
        for (int i = 0; i < 4; i++) o[nt][i] = 0.f;

    __syncthreads();

    unsigned aq[4][4];
    #pragma unroll
    for (int ks = 0; ks < 4; ks++)
        ldsm_x4(aq[ks][0], aq[ks][1], aq[ks][2], aq[ks][3], q_lm + ks*32);

    const int NKT = S_/64;
    for (int kt = 0; kt < NKT; kt++) {
        int bi = kt & 1;
        cp_wait<0>();
        __syncthreads();
        if (kt + 1 < NKT) issue_kv(bi ^ 1, kt + 1);

        float s[8][4];
        #pragma unroll
        for (int nt = 0; nt < 8; nt++)
            #pragma unroll
            for (int i = 0; i < 4; i++) s[nt][i] = 0.f;
        #pragma unroll
        for (int ks = 0; ks < 4; ks++) {
            unsigned bf[8][2];
            #pragma unroll
            for (int p = 0; p < 4; p++)
                ldsm_x4(bf[2*p][0], bf[2*p][1], bf[2*p+1][0], bf[2*p+1][1],
                        k_lm[bi][p] + ks*32);
            #pragma unroll
            for (int nt = 0; nt < 8; nt++)
                mma_f16(s[nt], aq[ks], bf[nt]);
        }

        #pragma unroll
        for (int r = 0; r < 2; r++) {
            float mx = -1e30f;
            #pragma unroll
            for (int nt = 0; nt < 8; nt++)
                mx = fmaxf(mx, fmaxf(s[nt][2*r], s[nt][2*r+1]));
            mx = fmaxf(mx, __shfl_xor_sync(0xffffffffu, mx, 1));
            mx = fmaxf(mx, __shfl_xor_sync(0xffffffffu, mx, 2));
            float mn = fmaxf(m_r[r], mx);
            float cr = fast_exp2(m_r[r] - mn);
            m_r[r] = mn;
            float ls = 0.f;
            #pragma unroll
            for (int nt = 0; nt < 8; nt++) {
                float p0 = fast_exp2(s[nt][2*r    ] - mn);
                float p1 = fast_exp2(s[nt][2*r + 1] - mn);
                s[nt][2*r] = p0; s[nt][2*r+1] = p1;
                ls += p0 + p1;
            }
            ls += __shfl_xor_sync(0xffffffffu, ls, 1);
            ls += __shfl_xor_sync(0xffffffffu, ls, 2);
            l_r[r] = l_r[r] * cr + ls;
            #pragma unroll
            for (int nt = 0; nt < 8; nt++) {
                o[nt][2*r] *= cr; o[nt][2*r+1] *= cr;
            }
        }

        unsigned pa[4][4];
        #pragma unroll
        for (int ks = 0; ks < 4; ks++) {
            pa[ks][0] = pack_h2(s[2*ks  ][0], s[2*ks  ][1]);
            pa[ks][1] = pack_h2(s[2*ks  ][2], s[2*ks  ][3]);
            pa[ks][2] = pack_h2(s[2*ks+1][0], s[2*ks+1][1]);
            pa[ks][3] = pack_h2(s[2*ks+1][2], s[2*ks+1][3]);
        }

        #pragma unroll
        for (int ks = 0; ks < 4; ks++) {
            unsigned vf[8][2];
            #pragma unroll
            for (int dp = 0; dp < 4; dp++)
                ldsm_x4_trans(vf[2*dp][0], vf[2*dp][1], vf[2*dp+1][0], vf[2*dp+1][1],
                              v_lm[bi][ks][dp]);
            #pragma unroll
            for (int nt = 0; nt < 8; nt++)
                mma_f16(o[nt], pa[ks], vf[nt]);
        }
    }

    float inv0 = 1.0f / l_r[0];
    float inv1 = 1.0f / l_r[1];
    int row0 = bb*S_ + q0 + m0 + g;
    int row1 = row0 + 8;
    #pragma unroll
    for (int nt = 0; nt < 8; nt++) {
        int d = nt * 8 + tg * 2;
        *(__half2*)&ctx[((size_t)(row0*H_ + hh))*DH_ + d] =
            __floats2half2_rn(o[nt][0] * inv0, o[nt][1] * inv0);
        *(__half2*)&ctx[((size_t)(row1*H_ + hh))*DH_ + d] =
            __floats2half2_rn(o[nt][2] * inv1, o[nt][3] * inv1);
    }
}

// ---------------------------------------------------------------------------
// Launcher
// ---------------------------------------------------------------------------
extern "C" void kernel_launch(void* const* d_in, const int* in_sizes, int n_in,
                              void* d_out, int out_size)
{
    const float* x   = (const float*)d_in[0];
    const float* Wq  = (const float*)d_in[1];
    const float* bq  = (const float*)d_in[2];
    const float* Wk  = (const float*)d_in[3];
    const float* bk  = (const float*)d_in[4];
    const float* Wv  = (const float*)d_in[5];
    const float* bv  = (const float*)d_in[6];
    const float* Wo  = (const float*)d_in[7];
    const float* bo  = (const float*)d_in[8];
    const float* g1  = (const float*)d_in[9];
    const float* be1 = (const float*)d_in[10];
    const float* g2  = (const float*)d_in[11];
    const float* be2 = (const float*)d_in[12];
    const float* W1  = (const float*)d_in[13];
    const float* b1  = (const float*)d_in[14];
    const float* W2  = (const float*)d_in[15];
    const float* b2  = (const float*)d_in[16];
    float* out = (float*)d_out;

    __half *h, *q, *k, *v, *ctx, *ln2, *act, *wt;
    float *x2;
    cudaGetSymbolAddress((void**)&h,   g_h);
    cudaGetSymbolAddress((void**)&q,   g_q);
    cudaGetSymbolAddress((void**)&k,   g_k);
    cudaGetSymbolAddress((void**)&v,   g_v);
    cudaGetSymbolAddress((void**)&ctx, g_ctx);
    cudaGetSymbolAddress((void**)&x2,  g_x2);
    cudaGetSymbolAddress((void**)&ln2, g_ln2);
    cudaGetSymbolAddress((void**)&act, g_act);
    cudaGetSymbolAddress((void**)&wt,  g_wt);

    cudaFuncSetAttribute(h_gemm_kernel<EPI_ADD>,
                         cudaFuncAttributeMaxDynamicSharedMemorySize, GEMM_SMEM_BYTES);
    cudaFuncSetAttribute(h_gemm_kernel<EPI_GELU>,
                         cudaFuncAttributeMaxDynamicSharedMemorySize, GEMM_SMEM_BYTES);
    cudaFuncSetAttribute(h_qkv_kernel,
                         cudaFuncAttributeMaxDynamicSharedMemorySize, GEMM_SMEM_BYTES);
    cudaFuncSetAttribute(attn_kernel,
                         cudaFuncAttributeMaxDynamicSharedMemorySize, ATTN_SMEM_BYTES);

    // 0+1. fused prep: LN1 (blocks 0..1023) || weight convert (blocks 1024..)
    prep_kernel<<<LN_BLKS + CV_BLKS, 256>>>(x, g1, be1, h,
                                            Wq, Wk, Wv, Wo, W1, W2, wt);
    // 2. QKV (fp16 mma, batched; Q scaled by log2e/8 in epilogue)
    dim3 gqkv(D_/128, NROWS/128, 3);
    h_qkv_kernel<<<gqkv, 256, GEMM_SMEM_BYTES>>>(h, wt, bq, bk, bv, q, k, v);
    // 3. fused attention (exp2-domain softmax, MUFU.EX2) -> fp16 ctx
    dim3 gat(S_/128, H_, B_);
    attn_kernel<<<gat, 256, ATTN_SMEM_BYTES>>>(q, k, v, ctx);
    // 4. Wo projection + residual -> fp32 x2
    dim3 go(D_/128, NROWS/128);
    h_gemm_kernel<EPI_ADD><<<go, 256, GEMM_SMEM_BYTES>>>(ctx, wt + WT_O, bo, x, (void*)x2, NROWS, D_, D_);
    // 5. LN2 -> fp16 ln2
    ln_kernel<<<NROWS/8, 256>>>(x2, g2, be2, ln2);
    // 6. MLP up + exact GELU -> fp16 act
    dim3 gup(F_/128, NROWS/128);
    h_gemm_kernel<EPI_GELU><<<gup, 256, GEMM_SMEM_BYTES>>>(ln2, wt + WT_W1, b1, nullptr, (void*)act, NROWS, F_, D_);
    // 7. MLP down + bias + residual -> fp32 out
    dim3 gdn(D_/128, NROWS/128);
    h_gemm_kernel<EPI_ADD><<<gdn, 256, GEMM_SMEM_BYTES>>>(act, wt + WT_W2, b2, x2, (void*)out, NROWS, D_, F_);
}